// round 6
// baseline (speedup 1.0000x reference)
#include <cuda_runtime.h>
#include <math.h>

#define BS 4096
#define NE 128
#define NQ 32
#define CIN 256
#define EMB 512
#define INV_SQRT_HD 0.08838834764831843f

// ---- static scratch (allowed; no cudaMalloc anywhere) ----
static __device__ float g_k[268435456];   // [BS*128, 512]
static __device__ float g_v[268435456];   // [BS*128, 512]
static __device__ float g_q[67108864];    // [BS*32, 512]
static __device__ float g_att[67108864];  // [BS*32, 512]

// ---- packed f32x2 helpers ----
__device__ __forceinline__ unsigned long long pack2(float x, float y) {
    unsigned long long r; asm("mov.b64 %0, {%1, %2};" : "=l"(r) : "f"(x), "f"(y)); return r;
}
__device__ __forceinline__ void unpack2(unsigned long long u, float& x, float& y) {
    asm("mov.b64 {%0, %1}, %2;" : "=f"(x), "=f"(y) : "l"(u));
}
__device__ __forceinline__ unsigned long long ffma2(unsigned long long a, unsigned long long b, unsigned long long c) {
    unsigned long long d; asm("fma.rn.f32x2 %0, %1, %2, %3;" : "=l"(d) : "l"(a), "l"(b), "l"(c)); return d;
}

// =====================================================================
// Tiled GEMM: C[M,N] = A[M,K] @ B[N,K]^T   (B row-major [N,K])
// BM=BN=128, BK=16, 256 threads, 8x8 microtile via f32x2.
// MODE 0: KV projection (writes g_k for n<512, g_v for n>=512)
// MODE 1: Q projection (A-row remap: m -> (m/32)*128 + m%32)
// MODE 2: output projection (+bias, postmask zeroing; masks are int32!)
// =====================================================================
template<int MODE, int KDIM, int NDIM>
__global__ void __launch_bounds__(256) gemm_kernel(
    const float* __restrict__ A, const float* __restrict__ B,
    float* __restrict__ C, float* __restrict__ C2,
    const float* __restrict__ bias, const int* __restrict__ postmask)
{
    __shared__ float As[16][132];
    __shared__ float Bs[16][132];
    const int tid  = threadIdx.x;
    const int m0   = blockIdx.y * 128;
    const int n0   = blockIdx.x * 128;
    const int trow = tid >> 4;          // 0..15
    const int tcol = tid & 15;          // 0..15
    const int lm   = tid >> 2;          // 0..63
    const int lk4  = (tid & 3) * 4;     // 0,4,8,12

    unsigned long long acc[8][4];
#pragma unroll
    for (int i = 0; i < 8; ++i)
#pragma unroll
        for (int j = 0; j < 4; ++j) acc[i][j] = 0ull;

    for (int k0 = 0; k0 < KDIM; k0 += 16) {
#pragma unroll
        for (int h = 0; h < 2; ++h) {
            int m = lm + h * 64;
            int gm = m0 + m;
            long arow = (MODE == 1) ? ((long)(gm >> 5) * 128 + (gm & 31)) : (long)gm;
            float4 v = *(const float4*)(A + arow * KDIM + k0 + lk4);
            As[lk4 + 0][m] = v.x; As[lk4 + 1][m] = v.y;
            As[lk4 + 2][m] = v.z; As[lk4 + 3][m] = v.w;
        }
#pragma unroll
        for (int h = 0; h < 2; ++h) {
            int n = lm + h * 64;
            float4 v = *(const float4*)(B + (long)(n0 + n) * KDIM + k0 + lk4);
            Bs[lk4 + 0][n] = v.x; Bs[lk4 + 1][n] = v.y;
            Bs[lk4 + 2][n] = v.z; Bs[lk4 + 3][n] = v.w;
        }
        __syncthreads();
#pragma unroll
        for (int kk = 0; kk < 16; ++kk) {
            float4 a0 = *(const float4*)&As[kk][trow * 8];
            float4 a1 = *(const float4*)&As[kk][trow * 8 + 4];
            float4 b0 = *(const float4*)&Bs[kk][tcol * 8];
            float4 b1 = *(const float4*)&Bs[kk][tcol * 8 + 4];
            unsigned long long bp[4] = { pack2(b0.x, b0.y), pack2(b0.z, b0.w),
                                         pack2(b1.x, b1.y), pack2(b1.z, b1.w) };
            float a[8] = { a0.x, a0.y, a0.z, a0.w, a1.x, a1.y, a1.z, a1.w };
#pragma unroll
            for (int i = 0; i < 8; ++i) {
                unsigned long long ap = pack2(a[i], a[i]);
#pragma unroll
                for (int j = 0; j < 4; ++j) acc[i][j] = ffma2(ap, bp[j], acc[i][j]);
            }
        }
        __syncthreads();
    }

#pragma unroll
    for (int i = 0; i < 8; ++i) {
        int gm = m0 + trow * 8 + i;
        int gn = n0 + tcol * 8;
        float r[8];
#pragma unroll
        for (int j = 0; j < 4; ++j) unpack2(acc[i][j], r[2 * j], r[2 * j + 1]);
        if (MODE == 2) {
            bool z = (postmask[gm] != 0);
#pragma unroll
            for (int j = 0; j < 8; ++j) r[j] = z ? 0.0f : (r[j] + bias[gn + j]);
            float4* dst = (float4*)(C + (long)gm * NDIM + gn);
            dst[0] = make_float4(r[0], r[1], r[2], r[3]);
            dst[1] = make_float4(r[4], r[5], r[6], r[7]);
        } else if (MODE == 0) {
            float* base = (gn < 512) ? C : C2;
            int col = (gn < 512) ? gn : (gn - 512);
            float4* dst = (float4*)(base + (long)gm * 512 + col);
            dst[0] = make_float4(r[0], r[1], r[2], r[3]);
            dst[1] = make_float4(r[4], r[5], r[6], r[7]);
        } else {
            float4* dst = (float4*)(C + (long)gm * NDIM + gn);
            dst[0] = make_float4(r[0], r[1], r[2], r[3]);
            dst[1] = make_float4(r[4], r[5], r[6], r[7]);
        }
    }
}

// =====================================================================
// Attention: one CTA per (batch b, head h). 256 threads.
// smem rows strided 140 floats. premask is int32 (harness bool->i32).
// =====================================================================
#define SROW 140
#define SM_Q 0
#define SM_K (32 * SROW)
#define SM_V (160 * SROW)
#define SM_P (288 * SROW)
#define ATT_SMEM (320 * SROW * 4)

__global__ void __launch_bounds__(256) attn_kernel(
    const float* __restrict__ gq, const float* __restrict__ gk,
    const float* __restrict__ gv, const int* __restrict__ premask,
    float* __restrict__ gatt)
{
    extern __shared__ float sm[];
    const int b = blockIdx.x, h = blockIdx.y;
    const int tid = threadIdx.x;
    const int lane = tid & 31;
    const int q0 = (tid >> 5) * 4;

    for (int i = tid; i < 32 * 32; i += 256) {
        int q = i >> 5, d4 = i & 31;
        *(float4*)&sm[SM_Q + q * SROW + d4 * 4] =
            *(const float4*)(gq + ((long)(b * 32 + q)) * 512 + h * 128 + d4 * 4);
    }
    for (int i = tid; i < 128 * 32; i += 256) {
        int e = i >> 5, d4 = i & 31;
        long off = ((long)(b * 128 + e)) * 512 + h * 128 + d4 * 4;
        *(float4*)&sm[SM_K + e * SROW + d4 * 4] = *(const float4*)(gk + off);
        *(float4*)&sm[SM_V + e * SROW + d4 * 4] = *(const float4*)(gv + off);
    }
    __syncthreads();

    // logits: acc[qi][j] = Q[q0+qi] . K[lane+32j]
    float lg[4][4];
    {
        float acc[4][4];
#pragma unroll
        for (int qi = 0; qi < 4; ++qi)
#pragma unroll
            for (int j = 0; j < 4; ++j) acc[qi][j] = 0.0f;
        for (int d4 = 0; d4 < 32; ++d4) {
            float4 qa[4], ka[4];
#pragma unroll
            for (int qi = 0; qi < 4; ++qi) qa[qi] = *(const float4*)&sm[SM_Q + (q0 + qi) * SROW + d4 * 4];
#pragma unroll
            for (int j = 0; j < 4; ++j) ka[j] = *(const float4*)&sm[SM_K + (lane + 32 * j) * SROW + d4 * 4];
#pragma unroll
            for (int qi = 0; qi < 4; ++qi)
#pragma unroll
                for (int j = 0; j < 4; ++j)
                    acc[qi][j] += qa[qi].x * ka[j].x + qa[qi].y * ka[j].y
                                + qa[qi].z * ka[j].z + qa[qi].w * ka[j].w;
        }
        const int* pm = premask + (long)b * (32 * 128);
#pragma unroll
        for (int qi = 0; qi < 4; ++qi)
#pragma unroll
            for (int j = 0; j < 4; ++j) {
                int e = lane + 32 * j;
                lg[qi][j] = pm[(q0 + qi) * 128 + e] ? -INFINITY : acc[qi][j] * INV_SQRT_HD;
            }
    }

    // softmax per row (full-warp reductions; all lanes share the q-set)
#pragma unroll
    for (int qi = 0; qi < 4; ++qi) {
        float mx = fmaxf(fmaxf(lg[qi][0], lg[qi][1]), fmaxf(lg[qi][2], lg[qi][3]));
#pragma unroll
        for (int off = 16; off > 0; off >>= 1)
            mx = fmaxf(mx, __shfl_xor_sync(0xFFFFFFFFu, mx, off));
        float p[4], s = 0.0f;
        if (mx == -INFINITY) {
            p[0] = p[1] = p[2] = p[3] = 0.0f;
        } else {
#pragma unroll
            for (int j = 0; j < 4; ++j) { p[j] = __expf(lg[qi][j] - mx); s += p[j]; }
        }
#pragma unroll
        for (int off = 16; off > 0; off >>= 1)
            s += __shfl_xor_sync(0xFFFFFFFFu, s, off);
        float inv = (mx == -INFINITY) ? 0.0f : (1.0f / s);
#pragma unroll
        for (int j = 0; j < 4; ++j)
            sm[SM_P + (q0 + qi) * SROW + lane + 32 * j] = p[j] * inv;
    }
    __syncthreads();

    // out[q][d] = sum_e P[q][e] * V[e][d]
    float acc2[4][4];
#pragma unroll
    for (int qi = 0; qi < 4; ++qi)
#pragma unroll
        for (int j = 0; j < 4; ++j) acc2[qi][j] = 0.0f;
#pragma unroll 4
    for (int e = 0; e < 128; ++e) {
        float pf[4], vv[4];
#pragma unroll
        for (int qi = 0; qi < 4; ++qi) pf[qi] = sm[SM_P + (q0 + qi) * SROW + e];
#pragma unroll
        for (int j = 0; j < 4; ++j) vv[j] = sm[SM_V + e * SROW + lane + 32 * j];
#pragma unroll
        for (int qi = 0; qi < 4; ++qi)
#pragma unroll
            for (int j = 0; j < 4; ++j) acc2[qi][j] += pf[qi] * vv[j];
    }
#pragma unroll
    for (int qi = 0; qi < 4; ++qi)
#pragma unroll
        for (int j = 0; j < 4; ++j)
            gatt[((long)(b * 32 + q0 + qi)) * 512 + h * 128 + lane + 32 * j] = acc2[qi][j];
}

extern "C" void kernel_launch(void* const* d_in, const int* in_sizes, int n_in,
                              void* d_out, int out_size) {
    // Bind inputs by element count (all six are distinct) to be immune to
    // metadata ordering:
    //   entities 134217728, pre_mask 16777216, post_mask 131072,
    //   W_in 393216, W_out 262144, b_out 512
    const float* entities = nullptr; const int* pre_mask = nullptr;
    const int* post_mask = nullptr;  const float* W_in = nullptr;
    const float* W_out = nullptr;    const float* b_out = nullptr;
    for (int i = 0; i < n_in; ++i) {
        switch (in_sizes[i]) {
            case 134217728: entities  = (const float*)d_in[i]; break;
            case 16777216:  pre_mask  = (const int*)d_in[i];   break;
            case 131072:    post_mask = (const int*)d_in[i];   break;
            case 393216:    W_in      = (const float*)d_in[i]; break;
            case 262144:    W_out     = (const float*)d_in[i]; break;
            case 512:       b_out     = (const float*)d_in[i]; break;
        }
    }
    float* out = (float*)d_out;

    float *pk, *pv, *pq, *patt;
    cudaGetSymbolAddress((void**)&pk,   g_k);
    cudaGetSymbolAddress((void**)&pv,   g_v);
    cudaGetSymbolAddress((void**)&pq,   g_q);
    cudaGetSymbolAddress((void**)&patt, g_att);

    cudaFuncSetAttribute(attn_kernel, cudaFuncAttributeMaxDynamicSharedMemorySize, ATT_SMEM);

    // K/V projection: all 524288 entity rows, cols 512..1535 of W_in
    gemm_kernel<0, CIN, 1024><<<dim3(8, 4096), 256>>>(
        entities, W_in + 512 * CIN, pk, pv, nullptr, nullptr);
    // Q projection: only first 32 entities per batch, cols 0..511
    gemm_kernel<1, CIN, 512><<<dim3(4, 1024), 256>>>(
        entities, W_in, pq, nullptr, nullptr, nullptr);
    // attention
    attn_kernel<<<dim3(BS, 4), 256, ATT_SMEM>>>(pq, pk, pv, pre_mask, patt);
    // output projection + bias + post mask
    gemm_kernel<2, EMB, 512><<<dim3(4, 1024), 256>>>(
        patt, W_out, out, nullptr, b_out, post_mask);
}

// round 10
// speedup vs baseline: 1.0359x; 1.0359x over previous
#include <cuda_runtime.h>
#include <cuda_fp16.h>
#include <math.h>
#include <stdint.h>

#define BS 4096
#define CIN 256
#define INV_SQRT_HD 0.08838834764831843f

// ---- static scratch ----
static __device__ float g_k[268435456];   // [BS*128, 512]
static __device__ float g_v[268435456];   // [BS*128, 512]
static __device__ float g_q[67108864];    // [BS*32, 512]
static __device__ float g_att[67108864];  // [BS*32, 512]

// =====================================================================
// warp-level fp16 MMA (portable PTX, no 'a'-features)
// =====================================================================
__device__ __forceinline__ void mma16816(float* c, const uint32_t* a, const uint32_t* b) {
    asm volatile(
        "mma.sync.aligned.m16n8k16.row.col.f32.f16.f16.f32 "
        "{%0,%1,%2,%3}, {%4,%5,%6,%7}, {%8,%9}, {%0,%1,%2,%3};"
        : "+f"(c[0]), "+f"(c[1]), "+f"(c[2]), "+f"(c[3])
        : "r"(a[0]), "r"(a[1]), "r"(a[2]), "r"(a[3]), "r"(b[0]), "r"(b[1]));
}

// split fp32 -> (hi, lo) fp16 pair
__device__ __forceinline__ void split2(float x, __half& h, __half& l) {
    h = __float2half_rn(x);
    l = __float2half_rn(x - __half2float(h));
}
__device__ __forceinline__ uint32_t packh2(__half a, __half b) {
    __half2 t = __halves2half2(a, b);
    return *(uint32_t*)&t;
}

// =====================================================================
// 3xFP16 HMMA GEMM: C[M,N] = A[M,K] @ B[N,K]^T, fp32 in/out.
// Tile 128x128, BK=64, 256 threads (8 warps, each 64x32).
// MODE 0: KV proj (gn<512 -> C=g_k else C2=g_v col-512)
// MODE 1: Q proj (A row remap m -> (m/32)*128 + m%32)
// MODE 2: out proj (+bias, postmask zero)
// SMEM (half units, row stride 72): AH [128][72], AL, BH, BL
//   bytes: 4 * 128*72*2 = 73728. Epilogue reuses as fp32 [128][136].
// =====================================================================
#define HSTR 72
#define SM_AH 0
#define SM_AL (128 * HSTR)
#define SM_BH (256 * HSTR)
#define SM_BL (384 * HSTR)
#define GEMM_SMEM (512 * HSTR * 2)
#define DSTR 136

template<int MODE, int KDIM>
__global__ void __launch_bounds__(256) gemm_hmma(
    const float* __restrict__ A, const float* __restrict__ B,
    float* __restrict__ C, float* __restrict__ C2,
    const float* __restrict__ bias, const int* __restrict__ postmask)
{
    extern __shared__ __half sh[];
    const int tid  = threadIdx.x;
    const int m0   = blockIdx.y * 128;
    const int n0   = blockIdx.x * 128;
    const int wid  = tid >> 5, lane = tid & 31;
    const int wm   = wid & 1;          // 2 m-blocks of 64
    const int wn   = wid >> 1;         // 4 n-blocks of 32
    const int r    = lane >> 2;        // groupID 0..7
    const int tig  = lane & 3;         // thread-in-group

    float acc[4][4][4];
#pragma unroll
    for (int mt = 0; mt < 4; ++mt)
#pragma unroll
        for (int nt = 0; nt < 4; ++nt)
#pragma unroll
            for (int j = 0; j < 4; ++j) acc[mt][nt][j] = 0.0f;

    constexpr int NCH = KDIM / 64;
    for (int ch = 0; ch < NCH; ++ch) {
        const int k0 = ch * 64;
        // ---- stage chunk: fp32 gmem -> split fp16 smem ----
#pragma unroll
        for (int i = 0; i < 8; ++i) {
            int idx = tid + 256 * i;
            int row = idx >> 4;          // 0..127
            int q   = idx & 15;          // float4 index within 64-col chunk
            long arow = (MODE == 1) ? ((long)((m0 + row) >> 5) * 128 + ((m0 + row) & 31))
                                    : (long)(m0 + row);
            float4 va = *(const float4*)(A + arow * KDIM + k0 + q * 4);
            float4 vb = *(const float4*)(B + (long)(n0 + row) * KDIM + k0 + q * 4);
            __half h0, h1, h2, h3, l0, l1, l2, l3;
            split2(va.x, h0, l0); split2(va.y, h1, l1);
            split2(va.z, h2, l2); split2(va.w, h3, l3);
            *(uint2*)&sh[SM_AH + row * HSTR + q * 4] = make_uint2(packh2(h0, h1), packh2(h2, h3));
            *(uint2*)&sh[SM_AL + row * HSTR + q * 4] = make_uint2(packh2(l0, l1), packh2(l2, l3));
            split2(vb.x, h0, l0); split2(vb.y, h1, l1);
            split2(vb.z, h2, l2); split2(vb.w, h3, l3);
            *(uint2*)&sh[SM_BH + row * HSTR + q * 4] = make_uint2(packh2(h0, h1), packh2(h2, h3));
            *(uint2*)&sh[SM_BL + row * HSTR + q * 4] = make_uint2(packh2(l0, l1), packh2(l2, l3));
        }
        __syncthreads();

        // ---- compute: 4 k16 steps ----
#pragma unroll
        for (int ks = 0; ks < 4; ++ks) {
            const int kc = ks * 16 + tig * 2;
            uint32_t bh[4][2], bl[4][2];
#pragma unroll
            for (int nt = 0; nt < 4; ++nt) {
                int n = wn * 32 + nt * 8 + r;
                bh[nt][0] = *(const uint32_t*)&sh[SM_BH + n * HSTR + kc];
                bh[nt][1] = *(const uint32_t*)&sh[SM_BH + n * HSTR + kc + 8];
                bl[nt][0] = *(const uint32_t*)&sh[SM_BL + n * HSTR + kc];
                bl[nt][1] = *(const uint32_t*)&sh[SM_BL + n * HSTR + kc + 8];
            }
#pragma unroll
            for (int mt = 0; mt < 4; ++mt) {
                int ra0 = wm * 64 + mt * 16 + r;
                uint32_t ah[4], al[4];
                ah[0] = *(const uint32_t*)&sh[SM_AH + ra0 * HSTR + kc];
                ah[1] = *(const uint32_t*)&sh[SM_AH + (ra0 + 8) * HSTR + kc];
                ah[2] = *(const uint32_t*)&sh[SM_AH + ra0 * HSTR + kc + 8];
                ah[3] = *(const uint32_t*)&sh[SM_AH + (ra0 + 8) * HSTR + kc + 8];
                al[0] = *(const uint32_t*)&sh[SM_AL + ra0 * HSTR + kc];
                al[1] = *(const uint32_t*)&sh[SM_AL + (ra0 + 8) * HSTR + kc];
                al[2] = *(const uint32_t*)&sh[SM_AL + ra0 * HSTR + kc + 8];
                al[3] = *(const uint32_t*)&sh[SM_AL + (ra0 + 8) * HSTR + kc + 8];
#pragma unroll
                for (int nt = 0; nt < 4; ++nt) {
                    mma16816(acc[mt][nt], ah, bh[nt]);  // hi*hi
                    mma16816(acc[mt][nt], ah, bl[nt]);  // hi*lo
                    mma16816(acc[mt][nt], al, bh[nt]);  // lo*hi
                }
            }
        }
        __syncthreads();
    }

    // ---- epilogue: regs -> smem (row-major fp32) -> coalesced gmem ----
    float* sD = (float*)sh;
#pragma unroll
    for (int mt = 0; mt < 4; ++mt) {
#pragma unroll
        for (int nt = 0; nt < 4; ++nt) {
            int row = wm * 64 + mt * 16 + r;
            int col = wn * 32 + nt * 8 + tig * 2;
            *(float2*)&sD[row * DSTR + col]       = make_float2(acc[mt][nt][0], acc[mt][nt][1]);
            *(float2*)&sD[(row + 8) * DSTR + col] = make_float2(acc[mt][nt][2], acc[mt][nt][3]);
        }
    }
    __syncthreads();

#pragma unroll 4
    for (int i = 0; i < 16; ++i) {
        int idx = tid + 256 * i;
        int row = idx >> 5;
        int cc  = idx & 31;
        float4 v = *(float4*)&sD[row * DSTR + cc * 4];
        int gm = m0 + row, gn = n0 + cc * 4;
        if (MODE == 2) {
            if (postmask[gm]) { v.x = v.y = v.z = v.w = 0.0f; }
            else {
                float4 bb = *(const float4*)(bias + gn);
                v.x += bb.x; v.y += bb.y; v.z += bb.z; v.w += bb.w;
            }
            *(float4*)(C + (long)gm * 512 + gn) = v;
        } else if (MODE == 0) {
            if (gn < 512) *(float4*)(C  + (long)gm * 512 + gn)       = v;
            else          *(float4*)(C2 + (long)gm * 512 + gn - 512) = v;
        } else {
            *(float4*)(C + (long)gm * 512 + gn) = v;
        }
    }
}

// =====================================================================
// Attention (unchanged from passing R6 kernel): one CTA per (b, h).
// =====================================================================
#define SROW 140
#define SM_Q 0
#define SM_K (32 * SROW)
#define SM_V (160 * SROW)
#define SM_P (288 * SROW)
#define ATT_SMEM (320 * SROW * 4)

__global__ void __launch_bounds__(256) attn_kernel(
    const float* __restrict__ gq, const float* __restrict__ gk,
    const float* __restrict__ gv, const int* __restrict__ premask,
    float* __restrict__ gatt)
{
    extern __shared__ float sm[];
    const int b = blockIdx.x, h = blockIdx.y;
    const int tid = threadIdx.x;
    const int lane = tid & 31;
    const int q0 = (tid >> 5) * 4;

    for (int i = tid; i < 32 * 32; i += 256) {
        int q = i >> 5, d4 = i & 31;
        *(float4*)&sm[SM_Q + q * SROW + d4 * 4] =
            *(const float4*)(gq + ((long)(b * 32 + q)) * 512 + h * 128 + d4 * 4);
    }
    for (int i = tid; i < 128 * 32; i += 256) {
        int e = i >> 5, d4 = i & 31;
        long off = ((long)(b * 128 + e)) * 512 + h * 128 + d4 * 4;
        *(float4*)&sm[SM_K + e * SROW + d4 * 4] = *(const float4*)(gk + off);
        *(float4*)&sm[SM_V + e * SROW + d4 * 4] = *(const float4*)(gv + off);
    }
    __syncthreads();

    float lg[4][4];
    {
        float acc[4][4];
#pragma unroll
        for (int qi = 0; qi < 4; ++qi)
#pragma unroll
            for (int j = 0; j < 4; ++j) acc[qi][j] = 0.0f;
        for (int d4 = 0; d4 < 32; ++d4) {
            float4 qa[4], ka[4];
#pragma unroll
            for (int qi = 0; qi < 4; ++qi) qa[qi] = *(const float4*)&sm[SM_Q + (q0 + qi) * SROW + d4 * 4];
#pragma unroll
            for (int j = 0; j < 4; ++j) ka[j] = *(const float4*)&sm[SM_K + (lane + 32 * j) * SROW + d4 * 4];
#pragma unroll
            for (int qi = 0; qi < 4; ++qi)
#pragma unroll
                for (int j = 0; j < 4; ++j)
                    acc[qi][j] += qa[qi].x * ka[j].x + qa[qi].y * ka[j].y
                                + qa[qi].z * ka[j].z + qa[qi].w * ka[j].w;
        }
        const int* pm = premask + (long)b * (32 * 128);
#pragma unroll
        for (int qi = 0; qi < 4; ++qi)
#pragma unroll
            for (int j = 0; j < 4; ++j) {
                int e = lane + 32 * j;
                lg[qi][j] = pm[(q0 + qi) * 128 + e] ? -INFINITY : acc[qi][j] * INV_SQRT_HD;
            }
    }

#pragma unroll
    for (int qi = 0; qi < 4; ++qi) {
        float mx = fmaxf(fmaxf(lg[qi][0], lg[qi][1]), fmaxf(lg[qi][2], lg[qi][3]));
#pragma unroll
        for (int off = 16; off > 0; off >>= 1)
            mx = fmaxf(mx, __shfl_xor_sync(0xFFFFFFFFu, mx, off));
        float p[4], s = 0.0f;
        if (mx == -INFINITY) {
            p[0] = p[1] = p[2] = p[3] = 0.0f;
        } else {
#pragma unroll
            for (int j = 0; j < 4; ++j) { p[j] = __expf(lg[qi][j] - mx); s += p[j]; }
        }
#pragma unroll
        for (int off = 16; off > 0; off >>= 1)
            s += __shfl_xor_sync(0xFFFFFFFFu, s, off);
        float inv = (mx == -INFINITY) ? 0.0f : (1.0f / s);
#pragma unroll
        for (int j = 0; j < 4; ++j)
            sm[SM_P + (q0 + qi) * SROW + lane + 32 * j] = p[j] * inv;
    }
    __syncthreads();

    float acc2[4][4];
#pragma unroll
    for (int qi = 0; qi < 4; ++qi)
#pragma unroll
        for (int j = 0; j < 4; ++j) acc2[qi][j] = 0.0f;
#pragma unroll 4
    for (int e = 0; e < 128; ++e) {
        float pf[4], vv[4];
#pragma unroll
        for (int qi = 0; qi < 4; ++qi) pf[qi] = sm[SM_P + (q0 + qi) * SROW + e];
#pragma unroll
        for (int j = 0; j < 4; ++j) vv[j] = sm[SM_V + e * SROW + lane + 32 * j];
#pragma unroll
        for (int qi = 0; qi < 4; ++qi)
#pragma unroll
            for (int j = 0; j < 4; ++j) acc2[qi][j] += pf[qi] * vv[j];
    }
#pragma unroll
    for (int qi = 0; qi < 4; ++qi)
#pragma unroll
        for (int j = 0; j < 4; ++j)
            gatt[((long)(b * 32 + q0 + qi)) * 512 + h * 128 + lane + 32 * j] = acc2[qi][j];
}

extern "C" void kernel_launch(void* const* d_in, const int* in_sizes, int n_in,
                              void* d_out, int out_size) {
    const float* entities = nullptr; const int* pre_mask = nullptr;
    const int* post_mask = nullptr;  const float* W_in = nullptr;
    const float* W_out = nullptr;    const float* b_out = nullptr;
    for (int i = 0; i < n_in; ++i) {
        switch (in_sizes[i]) {
            case 134217728: entities  = (const float*)d_in[i]; break;
            case 16777216:  pre_mask  = (const int*)d_in[i];   break;
            case 131072:    post_mask = (const int*)d_in[i];   break;
            case 393216:    W_in      = (const float*)d_in[i]; break;
            case 262144:    W_out     = (const float*)d_in[i]; break;
            case 512:       b_out     = (const float*)d_in[i]; break;
        }
    }
    float* out = (float*)d_out;

    float *pk, *pv, *pq, *patt;
    cudaGetSymbolAddress((void**)&pk,   g_k);
    cudaGetSymbolAddress((void**)&pv,   g_v);
    cudaGetSymbolAddress((void**)&pq,   g_q);
    cudaGetSymbolAddress((void**)&patt, g_att);

    cudaFuncSetAttribute(gemm_hmma<0, 256>, cudaFuncAttributeMaxDynamicSharedMemorySize, GEMM_SMEM);
    cudaFuncSetAttribute(gemm_hmma<1, 256>, cudaFuncAttributeMaxDynamicSharedMemorySize, GEMM_SMEM);
    cudaFuncSetAttribute(gemm_hmma<2, 512>, cudaFuncAttributeMaxDynamicSharedMemorySize, GEMM_SMEM);
    cudaFuncSetAttribute(attn_kernel, cudaFuncAttributeMaxDynamicSharedMemorySize, ATT_SMEM);

    // K/V projection: 524288 rows x [256 -> 1024] (W_in rows 512..1535)
    gemm_hmma<0, 256><<<dim3(8, 4096), 256, GEMM_SMEM>>>(
        entities, W_in + 512 * CIN, pk, pv, nullptr, nullptr);
    // Q projection: 131072 rows (remapped) x [256 -> 512]
    gemm_hmma<1, 256><<<dim3(4, 1024), 256, GEMM_SMEM>>>(
        entities, W_in, pq, nullptr, nullptr, nullptr);
    // attention
    attn_kernel<<<dim3(BS, 4), 256, ATT_SMEM>>>(pq, pk, pv, pre_mask, patt);
    // output projection + bias + post mask
    gemm_hmma<2, 512><<<dim3(4, 1024), 256, GEMM_SMEM>>>(
        patt, W_out, out, nullptr, b_out, post_mask);
}

// round 13
// speedup vs baseline: 1.6848x; 1.6264x over previous
#include <cuda_runtime.h>
#include <cuda_fp16.h>
#include <math.h>
#include <stdint.h>

#define BS 4096
#define CIN 256
#define INV_SQRT_HD 0.08838834764831843f

// ---- static scratch ----
static __device__ float  g_k[268435456];    // [BS*128, 512] fp32
static __device__ float  g_v[268435456];    // [BS*128, 512] fp32
static __device__ float  g_q[67108864];     // [BS*32, 512] fp32
static __device__ __half g_eh[134217728];   // entities hi
static __device__ __half g_el[134217728];   // entities lo
static __device__ __half g_ath[67108864];   // attention out hi [BS*32, 512]
static __device__ __half g_atl[67108864];   // attention out lo
static __device__ __half g_wih[393216];     // W_in hi
static __device__ __half g_wil[393216];     // W_in lo
static __device__ __half g_woh[262144];     // W_out hi
static __device__ __half g_wol[262144];     // W_out lo

// =====================================================================
// helpers
// =====================================================================
__device__ __forceinline__ uint32_t cvta_shared_u32(const void* p) {
    uint32_t r;
    asm("{ .reg .u64 t; cvta.to.shared.u64 t, %1; cvt.u32.u64 %0, t; }" : "=r"(r) : "l"(p));
    return r;
}
__device__ __forceinline__ void mma16816(float* c, const uint32_t* a, const uint32_t* b) {
    asm volatile(
        "mma.sync.aligned.m16n8k16.row.col.f32.f16.f16.f32 "
        "{%0,%1,%2,%3}, {%4,%5,%6,%7}, {%8,%9}, {%0,%1,%2,%3};"
        : "+f"(c[0]), "+f"(c[1]), "+f"(c[2]), "+f"(c[3])
        : "r"(a[0]), "r"(a[1]), "r"(a[2]), "r"(a[3]), "r"(b[0]), "r"(b[1]));
}
__device__ __forceinline__ void split2(float x, __half& h, __half& l) {
    h = __float2half_rn(x);
    l = __float2half_rn(x - __half2float(h));
}
__device__ __forceinline__ uint32_t packh2(__half a, __half b) {
    __half2 t = __halves2half2(a, b);
    return *(uint32_t*)&t;
}
__device__ __forceinline__ void cp16(uint32_t dst, const void* src) {
    asm volatile("cp.async.cg.shared.global [%0], [%1], 16;" :: "r"(dst), "l"(src));
}

// =====================================================================
// split kernel: fp32 -> (hi, lo) fp16 arrays, vectorized x4
// =====================================================================
__global__ void __launch_bounds__(256) split_kernel(
    const float4* __restrict__ src, __half* __restrict__ h, __half* __restrict__ l, int n4)
{
    int i = blockIdx.x * 256 + threadIdx.x;
    if (i >= n4) return;
    float4 v = src[i];
    __half h0, h1, h2, h3, l0, l1, l2, l3;
    split2(v.x, h0, l0); split2(v.y, h1, l1);
    split2(v.z, h2, l2); split2(v.w, h3, l3);
    ((uint2*)h)[i] = make_uint2(packh2(h0, h1), packh2(h2, h3));
    ((uint2*)l)[i] = make_uint2(packh2(l0, l1), packh2(l2, l3));
}

// =====================================================================
// 3xFP16 HMMA GEMM, pre-split operands, cp.async 3-stage pipeline.
// C[M,N] = A[M,K] @ B[N,K]^T. Tile 128x128, BK=32, 256 threads.
// MODE 0: KV proj (gn<512 -> C else C2 col-512)
// MODE 1: Q proj (A row remap m -> (m/32)*128 + m%32)
// MODE 2: out proj (+bias, postmask zero)
// SMEM per stage (halves, row stride 40): AH[128][40] AL BH BL
//   = 4 * 5120 halves = 40960 B; 3 stages = 122880 B.
// =====================================================================
#define ASTR 40
#define STG_H 20480           // halves per stage
#define STG_B 40960           // bytes per stage
#define GEMM_SMEM 122880
#define DSTR 136

template<int MODE, int KDIM>
__global__ void __launch_bounds__(256) gemm_hmma(
    const __half* __restrict__ Ah, const __half* __restrict__ Al,
    const __half* __restrict__ Bh, const __half* __restrict__ Bl,
    float* __restrict__ C, float* __restrict__ C2,
    const float* __restrict__ bias, const int* __restrict__ postmask)
{
    extern __shared__ __half sh[];
    const uint32_t sbase = cvta_shared_u32(sh);
    const int tid  = threadIdx.x;
    const int m0   = blockIdx.y * 128;
    const int n0   = blockIdx.x * 128;
    const int wid  = tid >> 5, lane = tid & 31;
    const int wm   = wid & 1;
    const int wn   = wid >> 1;
    const int r    = lane >> 2;
    const int tig  = lane & 3;

    constexpr int NCH = KDIM / 32;

    // copy-thread mapping: 2048 16B-chunks per stage, 8 per thread
    // idx: mat = idx>>9 (0:AH 1:AL 2:BH 3:BL), row = (idx>>2)&127, c16 = idx&3
    auto stage_copy = [&](int ch, int s) {
        const int k0 = ch * 32;
#pragma unroll
        for (int i = 0; i < 8; ++i) {
            int idx = tid + 256 * i;
            int mat = idx >> 9;
            int row = (idx >> 2) & 127;
            int c16 = idx & 3;
            const __half* src;
            if (mat <= 1) {
                int gm = m0 + row;
                long arow = (MODE == 1) ? ((long)(gm >> 5) * 128 + (gm & 31)) : (long)gm;
                src = (mat == 0 ? Ah : Al) + arow * KDIM + k0 + c16 * 8;
            } else {
                src = (mat == 2 ? Bh : Bl) + (long)(n0 + row) * KDIM + k0 + c16 * 8;
            }
            cp16(sbase + s * STG_B + mat * 10240 + row * 80 + c16 * 16, src);
        }
        asm volatile("cp.async.commit_group;" ::: "memory");
    };

    float acc[4][4][4];
#pragma unroll
    for (int mt = 0; mt < 4; ++mt)
#pragma unroll
        for (int nt = 0; nt < 4; ++nt)
#pragma unroll
            for (int j = 0; j < 4; ++j) acc[mt][nt][j] = 0.0f;

    stage_copy(0, 0);
    stage_copy(1, 1);

    for (int ch = 0; ch < NCH; ++ch) {
        if (ch + 1 < NCH) asm volatile("cp.async.wait_group 1;" ::: "memory");
        else              asm volatile("cp.async.wait_group 0;" ::: "memory");
        __syncthreads();

        const int sb = (ch % 3) * STG_H;  // stage base in halves
#pragma unroll
        for (int ks = 0; ks < 2; ++ks) {
            const int kc = ks * 16 + tig * 2;
            uint32_t ah[4][4], al[4][4], bh[4][2], bl[4][2];
#pragma unroll
            for (int nt = 0; nt < 4; ++nt) {
                int n = wn * 32 + nt * 8 + r;
                bh[nt][0] = *(const uint32_t*)&sh[sb + 10240 + n * ASTR + kc];
                bh[nt][1] = *(const uint32_t*)&sh[sb + 10240 + n * ASTR + kc + 8];
                bl[nt][0] = *(const uint32_t*)&sh[sb + 15360 + n * ASTR + kc];
                bl[nt][1] = *(const uint32_t*)&sh[sb + 15360 + n * ASTR + kc + 8];
            }
#pragma unroll
            for (int mt = 0; mt < 4; ++mt) {
                int ra = wm * 64 + mt * 16 + r;
                ah[mt][0] = *(const uint32_t*)&sh[sb + ra * ASTR + kc];
                ah[mt][1] = *(const uint32_t*)&sh[sb + (ra + 8) * ASTR + kc];
                ah[mt][2] = *(const uint32_t*)&sh[sb + ra * ASTR + kc + 8];
                ah[mt][3] = *(const uint32_t*)&sh[sb + (ra + 8) * ASTR + kc + 8];
                al[mt][0] = *(const uint32_t*)&sh[sb + 5120 + ra * ASTR + kc];
                al[mt][1] = *(const uint32_t*)&sh[sb + 5120 + (ra + 8) * ASTR + kc];
                al[mt][2] = *(const uint32_t*)&sh[sb + 5120 + ra * ASTR + kc + 8];
                al[mt][3] = *(const uint32_t*)&sh[sb + 5120 + (ra + 8) * ASTR + kc + 8];
            }
            // three passes: 16 independent MMAs each -> no acc dependency chains
#pragma unroll
            for (int mt = 0; mt < 4; ++mt)
#pragma unroll
                for (int nt = 0; nt < 4; ++nt) mma16816(acc[mt][nt], ah[mt], bh[nt]);
#pragma unroll
            for (int mt = 0; mt < 4; ++mt)
#pragma unroll
                for (int nt = 0; nt < 4; ++nt) mma16816(acc[mt][nt], ah[mt], bl[nt]);
#pragma unroll
            for (int mt = 0; mt < 4; ++mt)
#pragma unroll
                for (int nt = 0; nt < 4; ++nt) mma16816(acc[mt][nt], al[mt], bh[nt]);
        }
        if (ch + 2 < NCH) stage_copy(ch + 2, (ch + 2) % 3);
    }

    // ---- epilogue: regs -> smem (row-major fp32) -> coalesced gmem ----
    __syncthreads();
    float* sD = (float*)sh;
#pragma unroll
    for (int mt = 0; mt < 4; ++mt) {
#pragma unroll
        for (int nt = 0; nt < 4; ++nt) {
            int row = wm * 64 + mt * 16 + r;
            int col = wn * 32 + nt * 8 + tig * 2;
            *(float2*)&sD[row * DSTR + col]       = make_float2(acc[mt][nt][0], acc[mt][nt][1]);
            *(float2*)&sD[(row + 8) * DSTR + col] = make_float2(acc[mt][nt][2], acc[mt][nt][3]);
        }
    }
    __syncthreads();

#pragma unroll 4
    for (int i = 0; i < 16; ++i) {
        int idx = tid + 256 * i;
        int row = idx >> 5;
        int cc  = idx & 31;
        float4 v = *(float4*)&sD[row * DSTR + cc * 4];
        int gm = m0 + row, gn = n0 + cc * 4;
        if (MODE == 2) {
            if (postmask[gm]) { v.x = v.y = v.z = v.w = 0.0f; }
            else {
                float4 bb = *(const float4*)(bias + gn);
                v.x += bb.x; v.y += bb.y; v.z += bb.z; v.w += bb.w;
            }
            *(float4*)(C + (long)gm * 512 + gn) = v;
        } else if (MODE == 0) {
            if (gn < 512) *(float4*)(C  + (long)gm * 512 + gn)       = v;
            else          *(float4*)(C2 + (long)gm * 512 + gn - 512) = v;
        } else {
            *(float4*)(C + (long)gm * 512 + gn) = v;
        }
    }
}

// =====================================================================
// Attention: one CTA per (b, h); output written as split fp16 (hi/lo)
// so the out-projection GEMM consumes it directly.
// =====================================================================
#define SROW 140
#define SM_Q 0
#define SM_K (32 * SROW)
#define SM_V (160 * SROW)
#define SM_P (288 * SROW)
#define ATT_SMEM (320 * SROW * 4)

__global__ void __launch_bounds__(256) attn_kernel(
    const float* __restrict__ gq, const float* __restrict__ gk,
    const float* __restrict__ gv, const int* __restrict__ premask,
    __half* __restrict__ ath, __half* __restrict__ atl)
{
    extern __shared__ float sm[];
    const int b = blockIdx.x, h = blockIdx.y;
    const int tid = threadIdx.x;
    const int lane = tid & 31;
    const int q0 = (tid >> 5) * 4;

    for (int i = tid; i < 32 * 32; i += 256) {
        int q = i >> 5, d4 = i & 31;
        *(float4*)&sm[SM_Q + q * SROW + d4 * 4] =
            *(const float4*)(gq + ((long)(b * 32 + q)) * 512 + h * 128 + d4 * 4);
    }
    for (int i = tid; i < 128 * 32; i += 256) {
        int e = i >> 5, d4 = i & 31;
        long off = ((long)(b * 128 + e)) * 512 + h * 128 + d4 * 4;
        *(float4*)&sm[SM_K + e * SROW + d4 * 4] = *(const float4*)(gk + off);
        *(float4*)&sm[SM_V + e * SROW + d4 * 4] = *(const float4*)(gv + off);
    }
    __syncthreads();

    float lg[4][4];
    {
        float acc[4][4];
#pragma unroll
        for (int qi = 0; qi < 4; ++qi)
#pragma unroll
            for (int j = 0; j < 4; ++j) acc[qi][j] = 0.0f;
        for (int d4 = 0; d4 < 32; ++d4) {
            float4 qa[4], ka[4];
#pragma unroll
            for (int qi = 0; qi < 4; ++qi) qa[qi] = *(const float4*)&sm[SM_Q + (q0 + qi) * SROW + d4 * 4];
#pragma unroll
            for (int j = 0; j < 4; ++j) ka[j] = *(const float4*)&sm[SM_K + (lane + 32 * j) * SROW + d4 * 4];
#pragma unroll
            for (int qi = 0; qi < 4; ++qi)
#pragma unroll
                for (int j = 0; j < 4; ++j)
                    acc[qi][j] += qa[qi].x * ka[j].x + qa[qi].y * ka[j].y
                                + qa[qi].z * ka[j].z + qa[qi].w * ka[j].w;
        }
        const int* pm = premask + (long)b * (32 * 128);
#pragma unroll
        for (int qi = 0; qi < 4; ++qi)
#pragma unroll
            for (int j = 0; j < 4; ++j) {
                int e = lane + 32 * j;
                lg[qi][j] = pm[(q0 + qi) * 128 + e] ? -INFINITY : acc[qi][j] * INV_SQRT_HD;
            }
    }

#pragma unroll
    for (int qi = 0; qi < 4; ++qi) {
        float mx = fmaxf(fmaxf(lg[qi][0], lg[qi][1]), fmaxf(lg[qi][2], lg[qi][3]));
#pragma unroll
        for (int off = 16; off > 0; off >>= 1)
            mx = fmaxf(mx, __shfl_xor_sync(0xFFFFFFFFu, mx, off));
        float p[4], s = 0.0f;
        if (mx == -INFINITY) {
            p[0] = p[1] = p[2] = p[3] = 0.0f;
        } else {
#pragma unroll
            for (int j = 0; j < 4; ++j) { p[j] = __expf(lg[qi][j] - mx); s += p[j]; }
        }
#pragma unroll
        for (int off = 16; off > 0; off >>= 1)
            s += __shfl_xor_sync(0xFFFFFFFFu, s, off);
        float inv = (mx == -INFINITY) ? 0.0f : (1.0f / s);
#pragma unroll
        for (int j = 0; j < 4; ++j)
            sm[SM_P + (q0 + qi) * SROW + lane + 32 * j] = p[j] * inv;
    }
    __syncthreads();

    float acc2[4][4];
#pragma unroll
    for (int qi = 0; qi < 4; ++qi)
#pragma unroll
        for (int j = 0; j < 4; ++j) acc2[qi][j] = 0.0f;
#pragma unroll 4
    for (int e = 0; e < 128; ++e) {
        float pf[4], vv[4];
#pragma unroll
        for (int qi = 0; qi < 4; ++qi) pf[qi] = sm[SM_P + (q0 + qi) * SROW + e];
#pragma unroll
        for (int j = 0; j < 4; ++j) vv[j] = sm[SM_V + e * SROW + lane + 32 * j];
#pragma unroll
        for (int qi = 0; qi < 4; ++qi)
#pragma unroll
            for (int j = 0; j < 4; ++j) acc2[qi][j] += pf[qi] * vv[j];
    }
#pragma unroll
    for (int qi = 0; qi < 4; ++qi)
#pragma unroll
        for (int j = 0; j < 4; ++j) {
            long idx = ((long)(b * 32 + q0 + qi)) * 512 + h * 128 + lane + 32 * j;
            __half hh, ll;
            split2(acc2[qi][j], hh, ll);
            ath[idx] = hh; atl[idx] = ll;
        }
}

extern "C" void kernel_launch(void* const* d_in, const int* in_sizes, int n_in,
                              void* d_out, int out_size) {
    const float* entities = nullptr; const int* pre_mask = nullptr;
    const int* post_mask = nullptr;  const float* W_in = nullptr;
    const float* W_out = nullptr;    const float* b_out = nullptr;
    for (int i = 0; i < n_in; ++i) {
        switch (in_sizes[i]) {
            case 134217728: entities  = (const float*)d_in[i]; break;
            case 16777216:  pre_mask  = (const int*)d_in[i];   break;
            case 131072:    post_mask = (const int*)d_in[i];   break;
            case 393216:    W_in      = (const float*)d_in[i]; break;
            case 262144:    W_out     = (const float*)d_in[i]; break;
            case 512:       b_out     = (const float*)d_in[i]; break;
        }
    }
    float* out = (float*)d_out;

    float *pk, *pv, *pq;
    __half *peh, *pel, *path, *patl, *pwih, *pwil, *pwoh, *pwol;
    cudaGetSymbolAddress((void**)&pk,   g_k);
    cudaGetSymbolAddress((void**)&pv,   g_v);
    cudaGetSymbolAddress((void**)&pq,   g_q);
    cudaGetSymbolAddress((void**)&peh,  g_eh);
    cudaGetSymbolAddress((void**)&pel,  g_el);
    cudaGetSymbolAddress((void**)&path, g_ath);
    cudaGetSymbolAddress((void**)&patl, g_atl);
    cudaGetSymbolAddress((void**)&pwih, g_wih);
    cudaGetSymbolAddress((void**)&pwil, g_wil);
    cudaGetSymbolAddress((void**)&pwoh, g_woh);
    cudaGetSymbolAddress((void**)&pwol, g_wol);

    cudaFuncSetAttribute(gemm_hmma<0, 256>, cudaFuncAttributeMaxDynamicSharedMemorySize, GEMM_SMEM);
    cudaFuncSetAttribute(gemm_hmma<1, 256>, cudaFuncAttributeMaxDynamicSharedMemorySize, GEMM_SMEM);
    cudaFuncSetAttribute(gemm_hmma<2, 512>, cudaFuncAttributeMaxDynamicSharedMemorySize, GEMM_SMEM);
    cudaFuncSetAttribute(attn_kernel, cudaFuncAttributeMaxDynamicSharedMemorySize, ATT_SMEM);

    // pre-split all fp32 operands into fp16 hi/lo (memory-bound, ~0.2 ms)
    split_kernel<<<131072, 256>>>((const float4*)entities, peh, pel, 33554432);
    split_kernel<<<384, 256>>>((const float4*)W_in, pwih, pwil, 98304);
    split_kernel<<<256, 256>>>((const float4*)W_out, pwoh, pwol, 65536);

    // K/V projection: 524288 rows x [256 -> 1024] (W_in rows 512..1535)
    gemm_hmma<0, 256><<<dim3(8, 4096), 256, GEMM_SMEM>>>(
        peh, pel, pwih + 512 * CIN, pwil + 512 * CIN, pk, pv, nullptr, nullptr);
    // Q projection: 131072 rows (remapped) x [256 -> 512]
    gemm_hmma<1, 256><<<dim3(4, 1024), 256, GEMM_SMEM>>>(
        peh, pel, pwih, pwil, pq, nullptr, nullptr, nullptr);
    // attention (emits split fp16)
    attn_kernel<<<dim3(BS, 4), 256, ATT_SMEM>>>(pq, pk, pv, pre_mask, path, patl);
    // output projection + bias + post mask
    gemm_hmma<2, 512><<<dim3(4, 1024), 256, GEMM_SMEM>>>(
        path, patl, pwoh, pwol, out, nullptr, b_out, post_mask);
}

// round 14
// speedup vs baseline: 1.8292x; 1.0857x over previous
#include <cuda_runtime.h>
#include <cuda_fp16.h>
#include <math.h>
#include <stdint.h>

#define BS 4096
#define CIN 256
#define INV_SQRT_HD 0.08838834764831843f

// ---- static scratch ----
static __device__ float  g_k[268435456];    // [BS*128, 512] fp32
static __device__ float  g_v[268435456];    // [BS*128, 512] fp32
static __device__ float  g_q[67108864];     // [BS*32, 512] fp32
static __device__ __half g_eh[134217728];   // entities hi
static __device__ __half g_el[134217728];   // entities lo
static __device__ __half g_ath[67108864];   // attention out hi [BS*32, 512]
static __device__ __half g_atl[67108864];   // attention out lo
static __device__ __half g_wih[393216];     // W_in hi
static __device__ __half g_wil[393216];     // W_in lo
static __device__ __half g_woh[262144];     // W_out hi
static __device__ __half g_wol[262144];     // W_out lo

// =====================================================================
// helpers
// =====================================================================
__device__ __forceinline__ uint32_t cvta_shared_u32(const void* p) {
    uint32_t r;
    asm("{ .reg .u64 t; cvta.to.shared.u64 t, %1; cvt.u32.u64 %0, t; }" : "=r"(r) : "l"(p));
    return r;
}
__device__ __forceinline__ void mma16816(float* c, const uint32_t* a, const uint32_t* b) {
    asm volatile(
        "mma.sync.aligned.m16n8k16.row.col.f32.f16.f16.f32 "
        "{%0,%1,%2,%3}, {%4,%5,%6,%7}, {%8,%9}, {%0,%1,%2,%3};"
        : "+f"(c[0]), "+f"(c[1]), "+f"(c[2]), "+f"(c[3])
        : "r"(a[0]), "r"(a[1]), "r"(a[2]), "r"(a[3]), "r"(b[0]), "r"(b[1]));
}
__device__ __forceinline__ void split2(float x, __half& h, __half& l) {
    h = __float2half_rn(x);
    l = __float2half_rn(x - __half2float(h));
}
__device__ __forceinline__ uint32_t packh2(__half a, __half b) {
    __half2 t = __halves2half2(a, b);
    return *(uint32_t*)&t;
}
__device__ __forceinline__ void cp16(uint32_t dst, const void* src) {
    asm volatile("cp.async.cg.shared.global [%0], [%1], 16;" :: "r"(dst), "l"(src));
}

// =====================================================================
// split kernel: fp32 -> (hi, lo) fp16 arrays, vectorized x4
// =====================================================================
__global__ void __launch_bounds__(256) split_kernel(
    const float4* __restrict__ src, __half* __restrict__ h, __half* __restrict__ l, int n4)
{
    int i = blockIdx.x * 256 + threadIdx.x;
    if (i >= n4) return;
    float4 v = src[i];
    __half h0, h1, h2, h3, l0, l1, l2, l3;
    split2(v.x, h0, l0); split2(v.y, h1, l1);
    split2(v.z, h2, l2); split2(v.w, h3, l3);
    ((uint2*)h)[i] = make_uint2(packh2(h0, h1), packh2(h2, h3));
    ((uint2*)l)[i] = make_uint2(packh2(l0, l1), packh2(l2, l3));
}

// =====================================================================
// 3xFP16 HMMA GEMM, pre-split operands, cp.async 2-stage double buffer,
// 2 CTAs per SM for cross-CTA latency hiding.
// C[M,N] = A[M,K] @ B[N,K]^T. Tile 128x128, BK=32, 256 threads.
// MODE 0: KV proj (gn<512 -> C else C2 col-512)
// MODE 1: Q proj (A row remap m -> (m/32)*128 + m%32)
// MODE 2: out proj (+bias, postmask zero)
// SMEM per stage (halves, row stride 40): AH[128][40] AL BH BL
//   = 4 * 5120 halves = 40960 B; 2 stages = 81920 B (2 CTAs/SM fit).
// =====================================================================
#define ASTR 40
#define STG_H 20480           // halves per stage
#define STG_B 40960           // bytes per stage
#define GEMM_SMEM 81920
#define DSTR 136

template<int MODE, int KDIM>
__global__ void __launch_bounds__(256, 2) gemm_hmma(
    const __half* __restrict__ Ah, const __half* __restrict__ Al,
    const __half* __restrict__ Bh, const __half* __restrict__ Bl,
    float* __restrict__ C, float* __restrict__ C2,
    const float* __restrict__ bias, const int* __restrict__ postmask)
{
    extern __shared__ __half sh[];
    const uint32_t sbase = cvta_shared_u32(sh);
    const int tid  = threadIdx.x;
    const int m0   = blockIdx.y * 128;
    const int n0   = blockIdx.x * 128;
    const int wid  = tid >> 5, lane = tid & 31;
    const int wm   = wid & 1;
    const int wn   = wid >> 1;
    const int r    = lane >> 2;
    const int tig  = lane & 3;

    constexpr int NCH = KDIM / 32;

    // copy-thread mapping: 2048 16B-chunks per stage, 8 per thread
    // idx: mat = idx>>9 (0:AH 1:AL 2:BH 3:BL), row = (idx>>2)&127, c16 = idx&3
    auto stage_copy = [&](int ch, int s) {
        const int k0 = ch * 32;
#pragma unroll
        for (int i = 0; i < 8; ++i) {
            int idx = tid + 256 * i;
            int mat = idx >> 9;
            int row = (idx >> 2) & 127;
            int c16 = idx & 3;
            const __half* src;
            if (mat <= 1) {
                int gm = m0 + row;
                long arow = (MODE == 1) ? ((long)(gm >> 5) * 128 + (gm & 31)) : (long)gm;
                src = (mat == 0 ? Ah : Al) + arow * KDIM + k0 + c16 * 8;
            } else {
                src = (mat == 2 ? Bh : Bl) + (long)(n0 + row) * KDIM + k0 + c16 * 8;
            }
            cp16(sbase + s * STG_B + mat * 10240 + row * 80 + c16 * 16, src);
        }
        asm volatile("cp.async.commit_group;" ::: "memory");
    };

    float acc[4][4][4];
#pragma unroll
    for (int mt = 0; mt < 4; ++mt)
#pragma unroll
        for (int nt = 0; nt < 4; ++nt)
#pragma unroll
            for (int j = 0; j < 4; ++j) acc[mt][nt][j] = 0.0f;

    stage_copy(0, 0);

    for (int ch = 0; ch < NCH; ++ch) {
        if (ch + 1 < NCH) {
            stage_copy(ch + 1, (ch + 1) & 1);
            asm volatile("cp.async.wait_group 1;" ::: "memory");
        } else {
            asm volatile("cp.async.wait_group 0;" ::: "memory");
        }
        __syncthreads();

        const int sb = (ch & 1) * STG_H;  // stage base in halves
#pragma unroll
        for (int ks = 0; ks < 2; ++ks) {
            const int kc = ks * 16 + tig * 2;
            uint32_t ah[4][4], al[4][4], bh[4][2], bl[4][2];
#pragma unroll
            for (int nt = 0; nt < 4; ++nt) {
                int n = wn * 32 + nt * 8 + r;
                bh[nt][0] = *(const uint32_t*)&sh[sb + 10240 + n * ASTR + kc];
                bh[nt][1] = *(const uint32_t*)&sh[sb + 10240 + n * ASTR + kc + 8];
                bl[nt][0] = *(const uint32_t*)&sh[sb + 15360 + n * ASTR + kc];
                bl[nt][1] = *(const uint32_t*)&sh[sb + 15360 + n * ASTR + kc + 8];
            }
#pragma unroll
            for (int mt = 0; mt < 4; ++mt) {
                int ra = wm * 64 + mt * 16 + r;
                ah[mt][0] = *(const uint32_t*)&sh[sb + ra * ASTR + kc];
                ah[mt][1] = *(const uint32_t*)&sh[sb + (ra + 8) * ASTR + kc];
                ah[mt][2] = *(const uint32_t*)&sh[sb + ra * ASTR + kc + 8];
                ah[mt][3] = *(const uint32_t*)&sh[sb + (ra + 8) * ASTR + kc + 8];
                al[mt][0] = *(const uint32_t*)&sh[sb + 5120 + ra * ASTR + kc];
                al[mt][1] = *(const uint32_t*)&sh[sb + 5120 + (ra + 8) * ASTR + kc];
                al[mt][2] = *(const uint32_t*)&sh[sb + 5120 + ra * ASTR + kc + 8];
                al[mt][3] = *(const uint32_t*)&sh[sb + 5120 + (ra + 8) * ASTR + kc + 8];
            }
            // three passes: 16 independent MMAs each -> no acc dependency chains
#pragma unroll
            for (int mt = 0; mt < 4; ++mt)
#pragma unroll
                for (int nt = 0; nt < 4; ++nt) mma16816(acc[mt][nt], ah[mt], bh[nt]);
#pragma unroll
            for (int mt = 0; mt < 4; ++mt)
#pragma unroll
                for (int nt = 0; nt < 4; ++nt) mma16816(acc[mt][nt], ah[mt], bl[nt]);
#pragma unroll
            for (int mt = 0; mt < 4; ++mt)
#pragma unroll
                for (int nt = 0; nt < 4; ++nt) mma16816(acc[mt][nt], al[mt], bh[nt]);
        }
        __syncthreads();   // protect stage buffer before next iter's cp.async overwrite
    }

    // ---- epilogue: regs -> smem (row-major fp32) -> coalesced gmem ----
    float* sD = (float*)sh;
#pragma unroll
    for (int mt = 0; mt < 4; ++mt) {
#pragma unroll
        for (int nt = 0; nt < 4; ++nt) {
            int row = wm * 64 + mt * 16 + r;
            int col = wn * 32 + nt * 8 + tig * 2;
            *(float2*)&sD[row * DSTR + col]       = make_float2(acc[mt][nt][0], acc[mt][nt][1]);
            *(float2*)&sD[(row + 8) * DSTR + col] = make_float2(acc[mt][nt][2], acc[mt][nt][3]);
        }
    }
    __syncthreads();

#pragma unroll 4
    for (int i = 0; i < 16; ++i) {
        int idx = tid + 256 * i;
        int row = idx >> 5;
        int cc  = idx & 31;
        float4 v = *(float4*)&sD[row * DSTR + cc * 4];
        int gm = m0 + row, gn = n0 + cc * 4;
        if (MODE == 2) {
            if (postmask[gm]) { v.x = v.y = v.z = v.w = 0.0f; }
            else {
                float4 bb = *(const float4*)(bias + gn);
                v.x += bb.x; v.y += bb.y; v.z += bb.z; v.w += bb.w;
            }
            *(float4*)(C + (long)gm * 512 + gn) = v;
        } else if (MODE == 0) {
            if (gn < 512) *(float4*)(C  + (long)gm * 512 + gn)       = v;
            else          *(float4*)(C2 + (long)gm * 512 + gn - 512) = v;
        } else {
            *(float4*)(C + (long)gm * 512 + gn) = v;
        }
    }
}

// =====================================================================
// Attention: one CTA per (b, h); output written as split fp16 (hi/lo)
// so the out-projection GEMM consumes it directly.
// =====================================================================
#define SROW 140
#define SM_Q 0
#define SM_K (32 * SROW)
#define SM_V (160 * SROW)
#define SM_P (288 * SROW)
#define ATT_SMEM (320 * SROW * 4)

__global__ void __launch_bounds__(256) attn_kernel(
    const float* __restrict__ gq, const float* __restrict__ gk,
    const float* __restrict__ gv, const int* __restrict__ premask,
    __half* __restrict__ ath, __half* __restrict__ atl)
{
    extern __shared__ float sm[];
    const int b = blockIdx.x, h = blockIdx.y;
    const int tid = threadIdx.x;
    const int lane = tid & 31;
    const int q0 = (tid >> 5) * 4;

    for (int i = tid; i < 32 * 32; i += 256) {
        int q = i >> 5, d4 = i & 31;
        *(float4*)&sm[SM_Q + q * SROW + d4 * 4] =
            *(const float4*)(gq + ((long)(b * 32 + q)) * 512 + h * 128 + d4 * 4);
    }
    for (int i = tid; i < 128 * 32; i += 256) {
        int e = i >> 5, d4 = i & 31;
        long off = ((long)(b * 128 + e)) * 512 + h * 128 + d4 * 4;
        *(float4*)&sm[SM_K + e * SROW + d4 * 4] = *(const float4*)(gk + off);
        *(float4*)&sm[SM_V + e * SROW + d4 * 4] = *(const float4*)(gv + off);
    }
    __syncthreads();

    float lg[4][4];
    {
        float acc[4][4];
#pragma unroll
        for (int qi = 0; qi < 4; ++qi)
#pragma unroll
            for (int j = 0; j < 4; ++j) acc[qi][j] = 0.0f;
        for (int d4 = 0; d4 < 32; ++d4) {
            float4 qa[4], ka[4];
#pragma unroll
            for (int qi = 0; qi < 4; ++qi) qa[qi] = *(const float4*)&sm[SM_Q + (q0 + qi) * SROW + d4 * 4];
#pragma unroll
            for (int j = 0; j < 4; ++j) ka[j] = *(const float4*)&sm[SM_K + (lane + 32 * j) * SROW + d4 * 4];
#pragma unroll
            for (int qi = 0; qi < 4; ++qi)
#pragma unroll
                for (int j = 0; j < 4; ++j)
                    acc[qi][j] += qa[qi].x * ka[j].x + qa[qi].y * ka[j].y
                                + qa[qi].z * ka[j].z + qa[qi].w * ka[j].w;
        }
        const int* pm = premask + (long)b * (32 * 128);
#pragma unroll
        for (int qi = 0; qi < 4; ++qi)
#pragma unroll
            for (int j = 0; j < 4; ++j) {
                int e = lane + 32 * j;
                lg[qi][j] = pm[(q0 + qi) * 128 + e] ? -INFINITY : acc[qi][j] * INV_SQRT_HD;
            }
    }

#pragma unroll
    for (int qi = 0; qi < 4; ++qi) {
        float mx = fmaxf(fmaxf(lg[qi][0], lg[qi][1]), fmaxf(lg[qi][2], lg[qi][3]));
#pragma unroll
        for (int off = 16; off > 0; off >>= 1)
            mx = fmaxf(mx, __shfl_xor_sync(0xFFFFFFFFu, mx, off));
        float p[4], s = 0.0f;
        if (mx == -INFINITY) {
            p[0] = p[1] = p[2] = p[3] = 0.0f;
        } else {
#pragma unroll
            for (int j = 0; j < 4; ++j) { p[j] = __expf(lg[qi][j] - mx); s += p[j]; }
        }
#pragma unroll
        for (int off = 16; off > 0; off >>= 1)
            s += __shfl_xor_sync(0xFFFFFFFFu, s, off);
        float inv = (mx == -INFINITY) ? 0.0f : (1.0f / s);
#pragma unroll
        for (int j = 0; j < 4; ++j)
            sm[SM_P + (q0 + qi) * SROW + lane + 32 * j] = p[j] * inv;
    }
    __syncthreads();

    float acc2[4][4];
#pragma unroll
    for (int qi = 0; qi < 4; ++qi)
#pragma unroll
        for (int j = 0; j < 4; ++j) acc2[qi][j] = 0.0f;
#pragma unroll 4
    for (int e = 0; e < 128; ++e) {
        float pf[4], vv[4];
#pragma unroll
        for (int qi = 0; qi < 4; ++qi) pf[qi] = sm[SM_P + (q0 + qi) * SROW + e];
#pragma unroll
        for (int j = 0; j < 4; ++j) vv[j] = sm[SM_V + e * SROW + lane + 32 * j];
#pragma unroll
        for (int qi = 0; qi < 4; ++qi)
#pragma unroll
            for (int j = 0; j < 4; ++j) acc2[qi][j] += pf[qi] * vv[j];
    }
#pragma unroll
    for (int qi = 0; qi < 4; ++qi)
#pragma unroll
        for (int j = 0; j < 4; ++j) {
            long idx = ((long)(b * 32 + q0 + qi)) * 512 + h * 128 + lane + 32 * j;
            __half hh, ll;
            split2(acc2[qi][j], hh, ll);
            ath[idx] = hh; atl[idx] = ll;
        }
}

extern "C" void kernel_launch(void* const* d_in, const int* in_sizes, int n_in,
                              void* d_out, int out_size) {
    const float* entities = nullptr; const int* pre_mask = nullptr;
    const int* post_mask = nullptr;  const float* W_in = nullptr;
    const float* W_out = nullptr;    const float* b_out = nullptr;
    for (int i = 0; i < n_in; ++i) {
        switch (in_sizes[i]) {
            case 134217728: entities  = (const float*)d_in[i]; break;
            case 16777216:  pre_mask  = (const int*)d_in[i];   break;
            case 131072:    post_mask = (const int*)d_in[i];   break;
            case 393216:    W_in      = (const float*)d_in[i]; break;
            case 262144:    W_out     = (const float*)d_in[i]; break;
            case 512:       b_out     = (const float*)d_in[i]; break;
        }
    }
    float* out = (float*)d_out;

    float *pk, *pv, *pq;
    __half *peh, *pel, *path, *patl, *pwih, *pwil, *pwoh, *pwol;
    cudaGetSymbolAddress((void**)&pk,   g_k);
    cudaGetSymbolAddress((void**)&pv,   g_v);
    cudaGetSymbolAddress((void**)&pq,   g_q);
    cudaGetSymbolAddress((void**)&peh,  g_eh);
    cudaGetSymbolAddress((void**)&pel,  g_el);
    cudaGetSymbolAddress((void**)&path, g_ath);
    cudaGetSymbolAddress((void**)&patl, g_atl);
    cudaGetSymbolAddress((void**)&pwih, g_wih);
    cudaGetSymbolAddress((void**)&pwil, g_wil);
    cudaGetSymbolAddress((void**)&pwoh, g_woh);
    cudaGetSymbolAddress((void**)&pwol, g_wol);

    cudaFuncSetAttribute(gemm_hmma<0, 256>, cudaFuncAttributeMaxDynamicSharedMemorySize, GEMM_SMEM);
    cudaFuncSetAttribute(gemm_hmma<1, 256>, cudaFuncAttributeMaxDynamicSharedMemorySize, GEMM_SMEM);
    cudaFuncSetAttribute(gemm_hmma<2, 512>, cudaFuncAttributeMaxDynamicSharedMemorySize, GEMM_SMEM);
    cudaFuncSetAttribute(attn_kernel, cudaFuncAttributeMaxDynamicSharedMemorySize, ATT_SMEM);

    // pre-split all fp32 operands into fp16 hi/lo (memory-bound, ~0.2 ms)
    split_kernel<<<131072, 256>>>((const float4*)entities, peh, pel, 33554432);
    split_kernel<<<384, 256>>>((const float4*)W_in, pwih, pwil, 98304);
    split_kernel<<<256, 256>>>((const float4*)W_out, pwoh, pwol, 65536);

    // K/V projection: 524288 rows x [256 -> 1024] (W_in rows 512..1535)
    gemm_hmma<0, 256><<<dim3(8, 4096), 256, GEMM_SMEM>>>(
        peh, pel, pwih + 512 * CIN, pwil + 512 * CIN, pk, pv, nullptr, nullptr);
    // Q projection: 131072 rows (remapped) x [256 -> 512]
    gemm_hmma<1, 256><<<dim3(4, 1024), 256, GEMM_SMEM>>>(
        peh, pel, pwih, pwil, pq, nullptr, nullptr, nullptr);
    // attention (emits split fp16)
    attn_kernel<<<dim3(BS, 4), 256, ATT_SMEM>>>(pq, pk, pv, pre_mask, path, patl);
    // output projection + bias + post mask
    gemm_hmma<2, 512><<<dim3(4, 1024), 256, GEMM_SMEM>>>(
        path, patl, pwoh, pwol, out, nullptr, b_out, post_mask);
}